// round 1
// baseline (speedup 1.0000x reference)
#include <cuda_runtime.h>
#include <cstddef>

#define NU_MAX 100000
#define NI_MAX 100000
#define E_MAX  1000000
#define DIMN   128

// ---------------- scratch (static __device__, no allocation) ----------------
__device__ int   g_cnt[3][NU_MAX + 1];
__device__ int   g_off[3][NU_MAX + 1];
__device__ int   g_cur[3][NU_MAX];
__device__ int   g_adj[3][E_MAX];
__device__ float g_meanB[(size_t)NI_MAX * DIMN];  // rel 0: user->item (buys)
__device__ float g_meanR[(size_t)NU_MAX * DIMN];  // rel 1: item->user (rev)
__device__ float g_meanT[(size_t)NI_MAX * DIMN];  // rel 2: tag->item (tags)
__device__ float g_Wc[DIMN * DIMN];               // 0.5*(Wr_buys + Wr_tags)

// ---------------- CSR build ----------------
__global__ void k_zero_cnt() {
    int i = blockIdx.x * blockDim.x + threadIdx.x;
    const int total = 3 * (NU_MAX + 1);
    if (i < total) ((int*)g_cnt)[i] = 0;
}

__global__ void k_hist(const int* __restrict__ dst, int E, int rel) {
    int e = blockIdx.x * blockDim.x + threadIdx.x;
    if (e < E) atomicAdd(&g_cnt[rel][dst[e]], 1);
}

// 3 blocks (one per relation), 1024 threads: looping Hillis-Steele exclusive scan
__global__ void k_scan(int n0, int n1, int n2) {
    int rel = blockIdx.x;
    int n = (rel == 0) ? n0 : (rel == 1) ? n1 : n2;
    __shared__ int sh[1024];
    __shared__ int carry;
    if (threadIdx.x == 0) carry = 0;
    __syncthreads();
    for (int base = 0; base < n; base += 1024) {
        int i = base + threadIdx.x;
        int v = (i < n) ? g_cnt[rel][i] : 0;
        sh[threadIdx.x] = v;
        __syncthreads();
        #pragma unroll
        for (int d = 1; d < 1024; d <<= 1) {
            int t = (threadIdx.x >= d) ? sh[threadIdx.x - d] : 0;
            __syncthreads();
            sh[threadIdx.x] += t;
            __syncthreads();
        }
        int c = carry;
        int excl = c + sh[threadIdx.x] - v;
        if (i < n) { g_off[rel][i] = excl; g_cur[rel][i] = excl; }
        __syncthreads();
        if (threadIdx.x == 1023) carry = c + sh[1023];
        __syncthreads();
    }
    if (threadIdx.x == 0) g_off[rel][n] = carry;
}

__global__ void k_fill(const int* __restrict__ src, const int* __restrict__ dst,
                       int E, int rel) {
    int e = blockIdx.x * blockDim.x + threadIdx.x;
    if (e < E) {
        int d = dst[e];
        int p = atomicAdd(&g_cur[rel][d], 1);
        g_adj[rel][p] = src[e];
    }
}

// ---------------- mean aggregation: one warp per dst node ----------------
__global__ void k_agg(const float* __restrict__ xsrc, int n_dst, int rel) {
    int w = (blockIdx.x * blockDim.x + threadIdx.x) >> 5;
    int lane = threadIdx.x & 31;
    if (w >= n_dst) return;
    const int* __restrict__ adj = g_adj[rel];
    int s0 = g_off[rel][w], s1 = g_off[rel][w + 1];
    float4 acc = make_float4(0.f, 0.f, 0.f, 0.f);
    for (int e = s0; e < s1; e++) {
        int s = __ldg(&adj[e]);
        float4 v = *(const float4*)(xsrc + (size_t)s * DIMN + lane * 4);
        acc.x += v.x; acc.y += v.y; acc.z += v.z; acc.w += v.w;
    }
    int deg = s1 - s0;
    float inv = 1.0f / (float)(deg > 0 ? deg : 1);
    acc.x *= inv; acc.y *= inv; acc.z *= inv; acc.w *= inv;
    float* mean = (rel == 0) ? g_meanB : (rel == 1) ? g_meanR : g_meanT;
    *(float4*)(mean + (size_t)w * DIMN + lane * 4) = acc;
}

// ---------------- combine Wr for item relations ----------------
__global__ void k_wc(const float* __restrict__ WrB, const float* __restrict__ WrT) {
    int i = blockIdx.x * blockDim.x + threadIdx.x;
    if (i < DIMN * DIMN) g_Wc[i] = 0.5f * (WrB[i] + WrT[i]);
}

// ---------------- multi-panel GEMM: C[M,128] = sum_p S[p]*A_p[M,128]@W_p[128,128] + bias
template <int NP>
__device__ __forceinline__ void gemm_core(
    const float* const* A, const float* const* W, const float* const* Bs,
    const float* S, float* __restrict__ C, int M)
{
    const int BM = 64, BK = 16;
    __shared__ float As[BM][BK + 1];
    __shared__ float Ws[BK][DIMN];

    int t  = threadIdx.x;
    int m0 = blockIdx.x * BM;
    int tr = t >> 5;          // warp id 0..7 -> rows tr*8..tr*8+7
    int tc = t & 31;          // cols tc*4..tc*4+3
    int lr  = t >> 2;         // A-tile load row 0..63
    int lc4 = (t & 3) * 4;    // A-tile load k offset 0/4/8/12
    int wkr = t >> 4;         // W-tile load row 0..15
    int wn  = (t & 15) * 4;   // W-tile load col 0..60

    float acc[8][4];
    #pragma unroll
    for (int i = 0; i < 8; i++)
        #pragma unroll
        for (int j = 0; j < 4; j++) acc[i][j] = 0.f;

    #pragma unroll
    for (int p = 0; p < NP; p++) {
        const float* Ap = A[p];
        const float* Wp = W[p];
        float s = S[p];
        for (int k0 = 0; k0 < DIMN; k0 += BK) {
            // load A tile (guarded on M)
            float4 av = make_float4(0.f, 0.f, 0.f, 0.f);
            int row = m0 + lr;
            if (row < M) av = *(const float4*)(Ap + (size_t)row * DIMN + k0 + lc4);
            As[lr][lc4 + 0] = av.x; As[lr][lc4 + 1] = av.y;
            As[lr][lc4 + 2] = av.z; As[lr][lc4 + 3] = av.w;
            // load W tile, scaled
            float4 w0 = *(const float4*)(Wp + (size_t)(k0 + wkr) * DIMN + wn);
            float4 w1 = *(const float4*)(Wp + (size_t)(k0 + wkr) * DIMN + wn + 64);
            Ws[wkr][wn + 0]  = s * w0.x; Ws[wkr][wn + 1]  = s * w0.y;
            Ws[wkr][wn + 2]  = s * w0.z; Ws[wkr][wn + 3]  = s * w0.w;
            Ws[wkr][wn + 64] = s * w1.x; Ws[wkr][wn + 65] = s * w1.y;
            Ws[wkr][wn + 66] = s * w1.z; Ws[wkr][wn + 67] = s * w1.w;
            __syncthreads();
            #pragma unroll
            for (int k = 0; k < BK; k++) {
                float4 w4 = *(const float4*)&Ws[k][tc * 4];
                #pragma unroll
                for (int i = 0; i < 8; i++) {
                    float a = As[tr * 8 + i][k];
                    acc[i][0] += a * w4.x;
                    acc[i][1] += a * w4.y;
                    acc[i][2] += a * w4.z;
                    acc[i][3] += a * w4.w;
                }
            }
            __syncthreads();
        }
    }

    // bias
    float b[4] = {0.f, 0.f, 0.f, 0.f};
    #pragma unroll
    for (int p = 0; p < NP; p++) {
        if (Bs[p]) {
            b[0] += S[p] * Bs[p][tc * 4 + 0];
            b[1] += S[p] * Bs[p][tc * 4 + 1];
            b[2] += S[p] * Bs[p][tc * 4 + 2];
            b[3] += S[p] * Bs[p][tc * 4 + 3];
        }
    }

    #pragma unroll
    for (int i = 0; i < 8; i++) {
        int row = m0 + tr * 8 + i;
        if (row < M) {
            float4 o = make_float4(acc[i][0] + b[0], acc[i][1] + b[1],
                                   acc[i][2] + b[2], acc[i][3] + b[3]);
            *(float4*)(C + (size_t)row * DIMN + tc * 4) = o;
        }
    }
}

__global__ void __launch_bounds__(256)
k_gemm_user(const float* __restrict__ xu, const float* __restrict__ WlR,
            const float* __restrict__ WrR, const float* __restrict__ bR,
            float* __restrict__ C, int M) {
    const float* A[2]  = {g_meanR, xu};
    const float* W[2]  = {WlR, WrR};
    const float* Bs[2] = {bR, nullptr};
    const float  S[2]  = {1.f, 1.f};
    gemm_core<2>(A, W, Bs, S, C, M);
}

__global__ void __launch_bounds__(256)
k_gemm_item(const float* __restrict__ xi, const float* __restrict__ WlB,
            const float* __restrict__ bB, const float* __restrict__ WlT,
            const float* __restrict__ bT, float* __restrict__ C, int M) {
    const float* A[3]  = {g_meanB, g_meanT, xi};
    const float* W[3]  = {WlB, WlT, g_Wc};
    const float* Bs[3] = {bB, bT, nullptr};
    const float  S[3]  = {0.5f, 0.5f, 1.f};
    gemm_core<3>(A, W, Bs, S, C, M);
}

// ---------------- launch ----------------
extern "C" void kernel_launch(void* const* d_in, const int* in_sizes, int n_in,
                              void* d_out, int out_size) {
    const float* xu  = (const float*)d_in[0];
    const float* xi  = (const float*)d_in[1];
    const float* xt  = (const float*)d_in[2];
    const int*   eb  = (const int*)d_in[3];
    const int*   er  = (const int*)d_in[4];
    const int*   et  = (const int*)d_in[5];
    const float* WlB = (const float*)d_in[6];
    const float* WrB = (const float*)d_in[7];
    const float* bB  = (const float*)d_in[8];
    const float* WlR = (const float*)d_in[9];
    const float* WrR = (const float*)d_in[10];
    const float* bR  = (const float*)d_in[11];
    const float* WlT = (const float*)d_in[12];
    const float* WrT = (const float*)d_in[13];
    const float* bT  = (const float*)d_in[14];

    int NU = in_sizes[0] / DIMN;
    int NI = in_sizes[1] / DIMN;
    int EB = in_sizes[3] / 2;
    int ER = in_sizes[4] / 2;
    int ET = in_sizes[5] / 2;

    float* out_user = (float*)d_out;
    float* out_item = (float*)d_out + (size_t)NU * DIMN;

    // CSR build
    k_zero_cnt<<<(3 * (NU_MAX + 1) + 255) / 256, 256>>>();
    k_hist<<<(EB + 255) / 256, 256>>>(eb + EB, EB, 0);
    k_hist<<<(ER + 255) / 256, 256>>>(er + ER, ER, 1);
    k_hist<<<(ET + 255) / 256, 256>>>(et + ET, ET, 2);
    k_scan<<<3, 1024>>>(NI, NU, NI);
    k_fill<<<(EB + 255) / 256, 256>>>(eb, eb + EB, EB, 0);
    k_fill<<<(ER + 255) / 256, 256>>>(er, er + ER, ER, 1);
    k_fill<<<(ET + 255) / 256, 256>>>(et, et + ET, ET, 2);

    // mean aggregation (one warp per dst node)
    k_agg<<<(NI * 32 + 255) / 256, 256>>>(xu, NI, 0);
    k_agg<<<(NU * 32 + 255) / 256, 256>>>(xi, NU, 1);
    k_agg<<<(NI * 32 + 255) / 256, 256>>>(xt, NI, 2);

    // combined root weight for item, then fused GEMMs
    k_wc<<<(DIMN * DIMN + 255) / 256, 256>>>(WrB, WrT);
    k_gemm_user<<<(NU + 63) / 64, 256>>>(xu, WlR, WrR, bR, out_user, NU);
    k_gemm_item<<<(NI + 63) / 64, 256>>>(xi, WlB, bB, WlT, bT, out_item, NI);
}

// round 2
// speedup vs baseline: 1.1221x; 1.1221x over previous
#include <cuda_runtime.h>
#include <cstddef>

#define NU_MAX 100000
#define NI_MAX 100000
#define E_MAX  1000000
#define DIMN   128

// ---------------- scratch (static __device__, no allocation) ----------------
__device__ int   g_cnt[3][NU_MAX + 1];
__device__ int   g_off[3][NU_MAX + 1];
__device__ int   g_cur[3][NU_MAX];
__device__ int   g_adj[3][E_MAX];
__device__ float g_meanB[(size_t)NI_MAX * DIMN];  // rel 0: user->item (buys)
__device__ float g_meanR[(size_t)NU_MAX * DIMN];  // rel 1: item->user (rev)
__device__ float g_meanT[(size_t)NI_MAX * DIMN];  // rel 2: tag->item (tags)
__device__ float g_Wc[DIMN * DIMN];               // 0.5*(Wr_buys + Wr_tags)

// ---------------- f32x2 helpers ----------------
__device__ __forceinline__ unsigned long long pack_dup(float x) {
    unsigned long long r;
    asm("mov.b64 %0, {%1, %1};" : "=l"(r) : "f"(x));
    return r;
}
__device__ __forceinline__ void fma2(unsigned long long& d,
                                     unsigned long long a, unsigned long long b) {
    asm("fma.rn.f32x2 %0, %1, %2, %0;" : "+l"(d) : "l"(a), "l"(b));
}
__device__ __forceinline__ float2 unpk(unsigned long long v) {
    float2 r;
    asm("mov.b64 {%0, %1}, %2;" : "=f"(r.x), "=f"(r.y) : "l"(v));
    return r;
}

// ---------------- CSR build ----------------
__global__ void k_zero_cnt() {
    int i = blockIdx.x * blockDim.x + threadIdx.x;
    const int total = 3 * (NU_MAX + 1);
    if (i < total) ((int*)g_cnt)[i] = 0;
}

__global__ void k_hist3(const int* __restrict__ db, const int* __restrict__ dr,
                        const int* __restrict__ dt, int EB, int ER, int ET) {
    int e = blockIdx.x * blockDim.x + threadIdx.x;
    if (e < EB) atomicAdd(&g_cnt[0][db[e]], 1);
    else if (e < EB + ER) atomicAdd(&g_cnt[1][dr[e - EB]], 1);
    else if (e < EB + ER + ET) atomicAdd(&g_cnt[2][dt[e - EB - ER]], 1);
}

// 3 blocks (one per relation), 1024 threads: looping Hillis-Steele exclusive scan
__global__ void k_scan(int n0, int n1, int n2) {
    int rel = blockIdx.x;
    int n = (rel == 0) ? n0 : (rel == 1) ? n1 : n2;
    __shared__ int sh[1024];
    __shared__ int carry;
    if (threadIdx.x == 0) carry = 0;
    __syncthreads();
    for (int base = 0; base < n; base += 1024) {
        int i = base + threadIdx.x;
        int v = (i < n) ? g_cnt[rel][i] : 0;
        sh[threadIdx.x] = v;
        __syncthreads();
        #pragma unroll
        for (int d = 1; d < 1024; d <<= 1) {
            int t = (threadIdx.x >= d) ? sh[threadIdx.x - d] : 0;
            __syncthreads();
            sh[threadIdx.x] += t;
            __syncthreads();
        }
        int c = carry;
        int excl = c + sh[threadIdx.x] - v;
        if (i < n) { g_off[rel][i] = excl; g_cur[rel][i] = excl; }
        __syncthreads();
        if (threadIdx.x == 1023) carry = c + sh[1023];
        __syncthreads();
    }
    if (threadIdx.x == 0) g_off[rel][n] = carry;
}

__global__ void k_fill3(const int* __restrict__ eb, const int* __restrict__ er,
                        const int* __restrict__ et, int EB, int ER, int ET) {
    int e = blockIdx.x * blockDim.x + threadIdx.x;
    int rel, idx;
    const int* ei;
    int E;
    if (e < EB) { rel = 0; idx = e; ei = eb; E = EB; }
    else if (e < EB + ER) { rel = 1; idx = e - EB; ei = er; E = ER; }
    else if (e < EB + ER + ET) { rel = 2; idx = e - EB - ER; ei = et; E = ET; }
    else return;
    int d = ei[E + idx];          // dst row
    int s = ei[idx];              // src row
    int p = atomicAdd(&g_cur[rel][d], 1);
    g_adj[rel][p] = s;
}

// ---------------- mean aggregation: one warp per dst node, all 3 relations ----------------
__global__ void k_agg3(const float* __restrict__ xu, const float* __restrict__ xi,
                       const float* __restrict__ xt, int NU, int NI) {
    int w = (blockIdx.x * blockDim.x + threadIdx.x) >> 5;
    int lane = threadIdx.x & 31;
    int rel, node;
    const float* xs;
    float* mean;
    if (w < NI) { rel = 0; node = w; xs = xu; mean = g_meanB; }
    else if (w < NI + NU) { rel = 1; node = w - NI; xs = xi; mean = g_meanR; }
    else if (w < NI + NU + NI) { rel = 2; node = w - NI - NU; xs = xt; mean = g_meanT; }
    else return;

    const int* __restrict__ adj = g_adj[rel];
    int s0 = g_off[rel][node], s1 = g_off[rel][node + 1];
    float4 acc0 = make_float4(0.f, 0.f, 0.f, 0.f);
    float4 acc1 = make_float4(0.f, 0.f, 0.f, 0.f);
    int e = s0;
    for (; e + 1 < s1; e += 2) {
        int a = __ldg(&adj[e]);
        int b = __ldg(&adj[e + 1]);
        float4 v0 = *(const float4*)(xs + (size_t)a * DIMN + lane * 4);
        float4 v1 = *(const float4*)(xs + (size_t)b * DIMN + lane * 4);
        acc0.x += v0.x; acc0.y += v0.y; acc0.z += v0.z; acc0.w += v0.w;
        acc1.x += v1.x; acc1.y += v1.y; acc1.z += v1.z; acc1.w += v1.w;
    }
    if (e < s1) {
        int a = __ldg(&adj[e]);
        float4 v0 = *(const float4*)(xs + (size_t)a * DIMN + lane * 4);
        acc0.x += v0.x; acc0.y += v0.y; acc0.z += v0.z; acc0.w += v0.w;
    }
    acc0.x += acc1.x; acc0.y += acc1.y; acc0.z += acc1.z; acc0.w += acc1.w;
    int deg = s1 - s0;
    float inv = 1.0f / (float)(deg > 0 ? deg : 1);
    acc0.x *= inv; acc0.y *= inv; acc0.z *= inv; acc0.w *= inv;
    *(float4*)(mean + (size_t)node * DIMN + lane * 4) = acc0;
}

// ---------------- combine Wr for item relations ----------------
__global__ void k_wc(const float* __restrict__ WrB, const float* __restrict__ WrT) {
    int i = blockIdx.x * blockDim.x + threadIdx.x;
    if (i < DIMN * DIMN) g_Wc[i] = 0.5f * (WrB[i] + WrT[i]);
}

// ---------------- multi-panel GEMM with FFMA2 (packed f32x2) ----------------
// C[m0:m0+64, 0:128] = sum_p S[p]*A_p@W_p + bias
template <int NP>
__device__ __forceinline__ void gemm_core(
    const float* const* A, const float* const* W, const float* const* Bs,
    const float* S, float* __restrict__ C, int M, int m0)
{
    const int BM = 64, BK = 16;
    __shared__ float As[BK][BM + 2];   // transposed: [k][row], +2 pad (keeps 8B align)
    __shared__ float Ws[BK][DIMN];

    int t  = threadIdx.x;
    int tr = t >> 5;          // warp id 0..7 -> rows tr*8 .. tr*8+7
    int tc = t & 31;          // cols tc*4 .. tc*4+3
    int lr  = t >> 2;         // A-tile load row 0..63
    int lc4 = (t & 3) * 4;    // A-tile load k offset 0/4/8/12
    int wkr = t >> 4;         // W-tile load row 0..15
    int wn  = (t & 15) * 4;   // W-tile load col 0..60

    // acc2[rp][j]: rows (tr*8+rp*2, tr*8+rp*2+1), col tc*4+j, packed f32x2
    unsigned long long acc2[4][4];
    #pragma unroll
    for (int i = 0; i < 4; i++)
        #pragma unroll
        for (int j = 0; j < 4; j++) acc2[i][j] = 0ull;

    #pragma unroll
    for (int p = 0; p < NP; p++) {
        const float* Ap = A[p];
        const float* Wp = W[p];
        float s = S[p];
        for (int k0 = 0; k0 < DIMN; k0 += BK) {
            // load A tile transposed (guarded on M)
            float4 av = make_float4(0.f, 0.f, 0.f, 0.f);
            int row = m0 + lr;
            if (row < M) av = *(const float4*)(Ap + (size_t)row * DIMN + k0 + lc4);
            As[lc4 + 0][lr] = av.x; As[lc4 + 1][lr] = av.y;
            As[lc4 + 2][lr] = av.z; As[lc4 + 3][lr] = av.w;
            // load W tile, scaled
            float4 w0 = *(const float4*)(Wp + (size_t)(k0 + wkr) * DIMN + wn);
            float4 w1 = *(const float4*)(Wp + (size_t)(k0 + wkr) * DIMN + wn + 64);
            Ws[wkr][wn + 0]  = s * w0.x; Ws[wkr][wn + 1]  = s * w0.y;
            Ws[wkr][wn + 2]  = s * w0.z; Ws[wkr][wn + 3]  = s * w0.w;
            Ws[wkr][wn + 64] = s * w1.x; Ws[wkr][wn + 65] = s * w1.y;
            Ws[wkr][wn + 66] = s * w1.z; Ws[wkr][wn + 67] = s * w1.w;
            __syncthreads();
            #pragma unroll
            for (int k = 0; k < BK; k++) {
                unsigned long long a2[4];
                #pragma unroll
                for (int rp = 0; rp < 4; rp++)
                    a2[rp] = *(const unsigned long long*)&As[k][tr * 8 + rp * 2];
                float4 w4 = *(const float4*)&Ws[k][tc * 4];
                unsigned long long wd0 = pack_dup(w4.x);
                unsigned long long wd1 = pack_dup(w4.y);
                unsigned long long wd2 = pack_dup(w4.z);
                unsigned long long wd3 = pack_dup(w4.w);
                #pragma unroll
                for (int rp = 0; rp < 4; rp++) {
                    fma2(acc2[rp][0], a2[rp], wd0);
                    fma2(acc2[rp][1], a2[rp], wd1);
                    fma2(acc2[rp][2], a2[rp], wd2);
                    fma2(acc2[rp][3], a2[rp], wd3);
                }
            }
            __syncthreads();
        }
    }

    // bias
    float b[4] = {0.f, 0.f, 0.f, 0.f};
    #pragma unroll
    for (int p = 0; p < NP; p++) {
        if (Bs[p]) {
            b[0] += S[p] * Bs[p][tc * 4 + 0];
            b[1] += S[p] * Bs[p][tc * 4 + 1];
            b[2] += S[p] * Bs[p][tc * 4 + 2];
            b[3] += S[p] * Bs[p][tc * 4 + 3];
        }
    }

    #pragma unroll
    for (int rp = 0; rp < 4; rp++) {
        float2 u0 = unpk(acc2[rp][0]);
        float2 u1 = unpk(acc2[rp][1]);
        float2 u2 = unpk(acc2[rp][2]);
        float2 u3 = unpk(acc2[rp][3]);
        int row0 = m0 + tr * 8 + rp * 2;
        if (row0 < M) {
            float4 o = make_float4(u0.x + b[0], u1.x + b[1], u2.x + b[2], u3.x + b[3]);
            *(float4*)(C + (size_t)row0 * DIMN + tc * 4) = o;
        }
        if (row0 + 1 < M) {
            float4 o = make_float4(u0.y + b[0], u1.y + b[1], u2.y + b[2], u3.y + b[3]);
            *(float4*)(C + (size_t)(row0 + 1) * DIMN + tc * 4) = o;
        }
    }
}

__global__ void __launch_bounds__(256)
k_gemm_all(const float* __restrict__ xu, const float* __restrict__ xi,
           const float* __restrict__ WlB, const float* __restrict__ bB,
           const float* __restrict__ WlR, const float* __restrict__ WrR,
           const float* __restrict__ bR,
           const float* __restrict__ WlT, const float* __restrict__ bT,
           float* __restrict__ out_user, float* __restrict__ out_item,
           int NU, int NI, int blocksU)
{
    if ((int)blockIdx.x < blocksU) {
        const float* A[2]  = {g_meanR, xu};
        const float* W[2]  = {WlR, WrR};
        const float* Bs[2] = {bR, nullptr};
        const float  S[2]  = {1.f, 1.f};
        gemm_core<2>(A, W, Bs, S, out_user, NU, blockIdx.x * 64);
    } else {
        const float* A[3]  = {g_meanB, g_meanT, xi};
        const float* W[3]  = {WlB, WlT, g_Wc};
        const float* Bs[3] = {bB, bT, nullptr};
        const float  S[3]  = {0.5f, 0.5f, 1.f};
        gemm_core<3>(A, W, Bs, S, out_item, NI, (blockIdx.x - blocksU) * 64);
    }
}

// ---------------- launch ----------------
extern "C" void kernel_launch(void* const* d_in, const int* in_sizes, int n_in,
                              void* d_out, int out_size) {
    const float* xu  = (const float*)d_in[0];
    const float* xi  = (const float*)d_in[1];
    const float* xt  = (const float*)d_in[2];
    const int*   eb  = (const int*)d_in[3];
    const int*   er  = (const int*)d_in[4];
    const int*   et  = (const int*)d_in[5];
    const float* WlB = (const float*)d_in[6];
    const float* WrB = (const float*)d_in[7];
    const float* bB  = (const float*)d_in[8];
    const float* WlR = (const float*)d_in[9];
    const float* WrR = (const float*)d_in[10];
    const float* bR  = (const float*)d_in[11];
    const float* WlT = (const float*)d_in[12];
    const float* WrT = (const float*)d_in[13];
    const float* bT  = (const float*)d_in[14];

    int NU = in_sizes[0] / DIMN;
    int NI = in_sizes[1] / DIMN;
    int EB = in_sizes[3] / 2;
    int ER = in_sizes[4] / 2;
    int ET = in_sizes[5] / 2;

    float* out_user = (float*)d_out;
    float* out_item = (float*)d_out + (size_t)NU * DIMN;

    int Etot = EB + ER + ET;

    // CSR build
    k_zero_cnt<<<(3 * (NU_MAX + 1) + 255) / 256, 256>>>();
    k_hist3<<<(Etot + 255) / 256, 256>>>(eb + EB, er + ER, et + ET, EB, ER, ET);
    k_scan<<<3, 1024>>>(NI, NU, NI);
    k_fill3<<<(Etot + 255) / 256, 256>>>(eb, er, et, EB, ER, ET);

    // mean aggregation (one warp per dst node, all relations)
    int totalNodes = NI + NU + NI;
    k_agg3<<<(totalNodes * 32 + 255) / 256, 256>>>(xu, xi, xt, NU, NI);

    // combined root weight for item, then fused GEMM (both outputs, one launch)
    k_wc<<<(DIMN * DIMN + 255) / 256, 256>>>(WrB, WrT);
    int blocksU = (NU + 63) / 64;
    int blocksI = (NI + 63) / 64;
    k_gemm_all<<<blocksU + blocksI, 256>>>(xu, xi, WlB, bB, WlR, WrR, bR, WlT, bT,
                                           out_user, out_item, NU, NI, blocksU);
}

// round 4
// speedup vs baseline: 1.3129x; 1.1700x over previous
#include <cuda_runtime.h>
#include <cuda_bf16.h>
#include <cstddef>
#include <cstdint>

#define NU_MAX 100000
#define NI_MAX 100000
#define E_MAX  1000000
#define DIMN   128

// ---------------- scratch (static __device__, no allocation) ----------------
__device__ int   g_cnt[3][NU_MAX + 1];
__device__ int   g_off[3][NU_MAX + 1];
__device__ int   g_cur[3][NU_MAX];
__device__ int   g_adj[3][E_MAX];
__device__ float g_meanB[(size_t)NI_MAX * DIMN];  // rel 0: user->item (buys)
__device__ float g_meanR[(size_t)NU_MAX * DIMN];  // rel 1: item->user (rev)
__device__ float g_meanT[(size_t)NI_MAX * DIMN];  // rel 2: tag->item (tags)

// split + transposed weights: [panel][half hi/lo][n*128+k] bf16
__device__ __align__(16) __nv_bfloat16 g_Wsp[5][2][DIMN * DIMN];
__device__ __align__(16) float g_biasU[DIMN];
__device__ __align__(16) float g_biasI[DIMN];

// ---------------- CSR build ----------------
__global__ void k_zero_cnt() {
    int i = blockIdx.x * blockDim.x + threadIdx.x;
    const int total = 3 * (NU_MAX + 1);
    if (i < total) ((int*)g_cnt)[i] = 0;
}

__global__ void k_hist3(const int* __restrict__ db, const int* __restrict__ dr,
                        const int* __restrict__ dt, int EB, int ER, int ET) {
    int e = blockIdx.x * blockDim.x + threadIdx.x;
    if (e < EB) atomicAdd(&g_cnt[0][db[e]], 1);
    else if (e < EB + ER) atomicAdd(&g_cnt[1][dr[e - EB]], 1);
    else if (e < EB + ER + ET) atomicAdd(&g_cnt[2][dt[e - EB - ER]], 1);
}

__global__ void k_scan(int n0, int n1, int n2) {
    int rel = blockIdx.x;
    int n = (rel == 0) ? n0 : (rel == 1) ? n1 : n2;
    __shared__ int sh[1024];
    __shared__ int carry;
    if (threadIdx.x == 0) carry = 0;
    __syncthreads();
    for (int base = 0; base < n; base += 1024) {
        int i = base + threadIdx.x;
        int v = (i < n) ? g_cnt[rel][i] : 0;
        sh[threadIdx.x] = v;
        __syncthreads();
        #pragma unroll
        for (int d = 1; d < 1024; d <<= 1) {
            int t = (threadIdx.x >= d) ? sh[threadIdx.x - d] : 0;
            __syncthreads();
            sh[threadIdx.x] += t;
            __syncthreads();
        }
        int c = carry;
        int excl = c + sh[threadIdx.x] - v;
        if (i < n) { g_off[rel][i] = excl; g_cur[rel][i] = excl; }
        __syncthreads();
        if (threadIdx.x == 1023) carry = c + sh[1023];
        __syncthreads();
    }
    if (threadIdx.x == 0) g_off[rel][n] = carry;
}

__global__ void k_fill3(const int* __restrict__ eb, const int* __restrict__ er,
                        const int* __restrict__ et, int EB, int ER, int ET) {
    int e = blockIdx.x * blockDim.x + threadIdx.x;
    int rel, idx;
    const int* ei;
    int E;
    if (e < EB) { rel = 0; idx = e; ei = eb; E = EB; }
    else if (e < EB + ER) { rel = 1; idx = e - EB; ei = er; E = ER; }
    else if (e < EB + ER + ET) { rel = 2; idx = e - EB - ER; ei = et; E = ET; }
    else return;
    int d = ei[E + idx];
    int s = ei[idx];
    int p = atomicAdd(&g_cur[rel][d], 1);
    g_adj[rel][p] = s;
}

// ---------------- mean aggregation: one warp per dst node ----------------
__global__ void k_agg3(const float* __restrict__ xu, const float* __restrict__ xi,
                       const float* __restrict__ xt, int NU, int NI) {
    int w = (blockIdx.x * blockDim.x + threadIdx.x) >> 5;
    int lane = threadIdx.x & 31;
    int rel, node;
    const float* xs;
    float* mean;
    if (w < NI) { rel = 0; node = w; xs = xu; mean = g_meanB; }
    else if (w < NI + NU) { rel = 1; node = w - NI; xs = xi; mean = g_meanR; }
    else if (w < NI + NU + NI) { rel = 2; node = w - NI - NU; xs = xt; mean = g_meanT; }
    else return;

    const int* __restrict__ adj = g_adj[rel];
    int s0 = g_off[rel][node], s1 = g_off[rel][node + 1];
    float4 acc0 = make_float4(0.f, 0.f, 0.f, 0.f);
    float4 acc1 = make_float4(0.f, 0.f, 0.f, 0.f);
    int e = s0;
    for (; e + 1 < s1; e += 2) {
        int a = __ldg(&adj[e]);
        int b = __ldg(&adj[e + 1]);
        float4 v0 = *(const float4*)(xs + (size_t)a * DIMN + lane * 4);
        float4 v1 = *(const float4*)(xs + (size_t)b * DIMN + lane * 4);
        acc0.x += v0.x; acc0.y += v0.y; acc0.z += v0.z; acc0.w += v0.w;
        acc1.x += v1.x; acc1.y += v1.y; acc1.z += v1.z; acc1.w += v1.w;
    }
    if (e < s1) {
        int a = __ldg(&adj[e]);
        float4 v0 = *(const float4*)(xs + (size_t)a * DIMN + lane * 4);
        acc0.x += v0.x; acc0.y += v0.y; acc0.z += v0.z; acc0.w += v0.w;
    }
    acc0.x += acc1.x; acc0.y += acc1.y; acc0.z += acc1.z; acc0.w += acc1.w;
    int deg = s1 - s0;
    float inv = 1.0f / (float)(deg > 0 ? deg : 1);
    acc0.x *= inv; acc0.y *= inv; acc0.z *= inv; acc0.w *= inv;
    *(float4*)(mean + (size_t)node * DIMN + lane * 4) = acc0;
}

// ---------------- weight prep: transpose, scale, bf16-split ----------------
__global__ void k_prepW(const float* __restrict__ WlR, const float* __restrict__ WrR,
                        const float* __restrict__ WlB, const float* __restrict__ WlT,
                        const float* __restrict__ WrB, const float* __restrict__ WrT,
                        const float* __restrict__ bR, const float* __restrict__ bB,
                        const float* __restrict__ bT) {
    int i = blockIdx.x * blockDim.x + threadIdx.x;
    if (i < 5 * 16384) {
        int panel = i >> 14;
        int e = i & 16383;
        int k = e >> 7;     // input dim 0..127
        int n = e & 127;    // output dim 0..127
        float v;
        switch (panel) {
            case 0:  v = WlR[k * 128 + n]; break;
            case 1:  v = WrR[k * 128 + n]; break;
            case 2:  v = 0.5f * WlB[k * 128 + n]; break;
            case 3:  v = 0.5f * WlT[k * 128 + n]; break;
            default: v = 0.5f * (WrB[k * 128 + n] + WrT[k * 128 + n]);
        }
        __nv_bfloat16 h = __float2bfloat16_rn(v);
        __nv_bfloat16 l = __float2bfloat16_rn(v - __bfloat162float(h));
        g_Wsp[panel][0][n * 128 + k] = h;   // transposed: [n][k]
        g_Wsp[panel][1][n * 128 + k] = l;
    }
    if (i < DIMN) {
        g_biasU[i] = bR[i];
        g_biasI[i] = 0.5f * (bB[i] + bT[i]);
    }
}

// ---------------- mma.sync helpers ----------------
__device__ __forceinline__ uint32_t smem_u32(const void* p) {
    uint32_t a;
    asm("{ .reg .u64 t; cvta.to.shared.u64 t, %1; cvt.u32.u64 %0, t; }"
        : "=r"(a) : "l"(p));
    return a;
}
__device__ __forceinline__ void ldsm4(uint32_t* r, uint32_t addr) {
    asm volatile("ldmatrix.sync.aligned.m8n8.x4.shared.b16 {%0,%1,%2,%3}, [%4];"
                 : "=r"(r[0]), "=r"(r[1]), "=r"(r[2]), "=r"(r[3]) : "r"(addr));
}
__device__ __forceinline__ void mma16816(float* d, const uint32_t* a,
                                         uint32_t b0, uint32_t b1) {
    asm volatile(
        "mma.sync.aligned.m16n8k16.row.col.f32.bf16.bf16.f32 "
        "{%0,%1,%2,%3}, {%4,%5,%6,%7}, {%8,%9}, {%0,%1,%2,%3};"
        : "+f"(d[0]), "+f"(d[1]), "+f"(d[2]), "+f"(d[3])
        : "r"(a[0]), "r"(a[1]), "r"(a[2]), "r"(a[3]), "r"(b0), "r"(b1));
}

// ---------------- tensor-core GEMM (mma.sync bf16 3-product split) ----------------
// smem tiles: Ah/Al [128 m][72 k] bf16, Wh/Wl [128 n][72 k] bf16
#define TSTRIDE 72   // elements; 144 bytes

__global__ void __launch_bounds__(256)
k_gemm_mma(const float* __restrict__ xu, const float* __restrict__ xi,
           float* __restrict__ out_user, float* __restrict__ out_item,
           int NU, int NI, int blocksU)
{
    extern __shared__ __nv_bfloat16 smem[];
    __nv_bfloat16* Ah = smem;                       // 128*72
    __nv_bfloat16* Al = Ah + 128 * TSTRIDE;
    __nv_bfloat16* Wh = Al + 128 * TSTRIDE;
    __nv_bfloat16* Wl = Wh + 128 * TSTRIDE;
    const uint32_t sAh = smem_u32(Ah);
    const uint32_t sAl = smem_u32(Al);
    const uint32_t sWh = smem_u32(Wh);
    const uint32_t sWl = smem_u32(Wl);

    int tid = threadIdx.x, w = tid >> 5, lane = tid & 31;
    bool isU = (int)blockIdx.x < blocksU;
    int bidl = isU ? blockIdx.x : (blockIdx.x - blocksU);
    int m0 = bidl * 128;
    int M  = isU ? NU : NI;
    int np = isU ? 2 : 3;
    const float* Ap[3];
    int wp[3];
    if (isU) { Ap[0] = g_meanR; Ap[1] = xu; Ap[2] = xu; wp[0] = 0; wp[1] = 1; wp[2] = 1; }
    else     { Ap[0] = g_meanB; Ap[1] = g_meanT; Ap[2] = xi; wp[0] = 2; wp[1] = 3; wp[2] = 4; }
    float* Cout = isU ? out_user : out_item;
    const float* bias = isU ? g_biasU : g_biasI;

    float acc[16][4];
    #pragma unroll
    for (int i = 0; i < 16; i++)
        #pragma unroll
        for (int j = 0; j < 4; j++) acc[i][j] = 0.f;

    // ldmatrix lane addressing (constant per thread)
    int a_row = lane & 15;            // row within m16
    int a_kh  = (lane >> 4) << 3;     // 0 or 8
    int b_n   = (lane & 7) + ((lane >> 4) << 3);   // 0..15
    int b_kh  = ((lane >> 3) & 1) << 3;            // 0 or 8

    for (int p = 0; p < np; p++) {
        const float* A = Ap[p];
        const __nv_bfloat16* WHsrc = g_Wsp[wp[p]][0];
        const __nv_bfloat16* WLsrc = g_Wsp[wp[p]][1];
        for (int c = 0; c < 2; c++) {
            __syncthreads();   // protect previous iteration's reads
            // ---- load & split A chunk [128 m x 64 k]
            #pragma unroll
            for (int it = 0; it < 8; it++) {
                int q = tid + it * 256;          // 0..2047
                int row = q >> 4;
                int k4  = (q & 15) << 2;
                int grow = m0 + row;
                float4 v = make_float4(0.f, 0.f, 0.f, 0.f);
                if (grow < M) v = *(const float4*)(A + (size_t)grow * DIMN + c * 64 + k4);
                __nv_bfloat16 h0 = __float2bfloat16_rn(v.x);
                __nv_bfloat16 h1 = __float2bfloat16_rn(v.y);
                __nv_bfloat16 h2 = __float2bfloat16_rn(v.z);
                __nv_bfloat16 h3 = __float2bfloat16_rn(v.w);
                ushort4 uh = make_ushort4(__bfloat16_as_ushort(h0), __bfloat16_as_ushort(h1),
                                          __bfloat16_as_ushort(h2), __bfloat16_as_ushort(h3));
                __nv_bfloat16 l0 = __float2bfloat16_rn(v.x - __bfloat162float(h0));
                __nv_bfloat16 l1 = __float2bfloat16_rn(v.y - __bfloat162float(h1));
                __nv_bfloat16 l2 = __float2bfloat16_rn(v.z - __bfloat162float(h2));
                __nv_bfloat16 l3 = __float2bfloat16_rn(v.w - __bfloat162float(h3));
                ushort4 ul = make_ushort4(__bfloat16_as_ushort(l0), __bfloat16_as_ushort(l1),
                                          __bfloat16_as_ushort(l2), __bfloat16_as_ushort(l3));
                *(ushort4*)(Ah + row * TSTRIDE + k4) = uh;
                *(ushort4*)(Al + row * TSTRIDE + k4) = ul;
            }
            // ---- copy W chunk [128 n x 64 k], hi + lo
            #pragma unroll
            for (int it = 0; it < 4; it++) {
                int q = tid + it * 256;          // 0..1023
                int n = q >> 3;
                int j = q & 7;                   // 8 bf16 units
                uint4 vh = *(const uint4*)(WHsrc + n * 128 + c * 64 + j * 8);
                uint4 vl = *(const uint4*)(WLsrc + n * 128 + c * 64 + j * 8);
                *(uint4*)(Wh + n * TSTRIDE + j * 8) = vh;
                *(uint4*)(Wl + n * TSTRIDE + j * 8) = vl;
            }
            __syncthreads();
            // ---- compute: warp w owns rows [w*16, w*16+16)
            #pragma unroll
            for (int ks = 0; ks < 4; ks++) {
                uint32_t aH[4], aL[4];
                uint32_t aoff = (w * 16 + a_row) * (TSTRIDE * 2) + (ks * 16 + a_kh) * 2;
                ldsm4(aH, sAh + aoff);
                ldsm4(aL, sAl + aoff);
                #pragma unroll
                for (int nt = 0; nt < 8; nt++) {
                    uint32_t bH[4], bL[4];
                    uint32_t boff = (nt * 16 + b_n) * (TSTRIDE * 2) + (ks * 16 + b_kh) * 2;
                    ldsm4(bH, sWh + boff);
                    ldsm4(bL, sWl + boff);
                    mma16816(acc[nt * 2],     aH, bH[0], bH[1]);
                    mma16816(acc[nt * 2 + 1], aH, bH[2], bH[3]);
                    mma16816(acc[nt * 2],     aH, bL[0], bL[1]);
                    mma16816(acc[nt * 2 + 1], aH, bL[2], bL[3]);
                    mma16816(acc[nt * 2],     aL, bH[0], bH[1]);
                    mma16816(acc[nt * 2 + 1], aL, bH[2], bH[3]);
                }
            }
        }
    }

    // ---- epilogue
    int row0 = m0 + w * 16 + (lane >> 2);
    int row1 = row0 + 8;
    int ncol = (lane & 3) * 2;
    #pragma unroll
    for (int t8 = 0; t8 < 16; t8++) {
        int n = t8 * 8 + ncol;
        float2 bv = *(const float2*)(bias + n);
        if (row0 < M) {
            float2 o = make_float2(acc[t8][0] + bv.x, acc[t8][1] + bv.y);
            *(float2*)(Cout + (size_t)row0 * DIMN + n) = o;
        }
        if (row1 < M) {
            float2 o = make_float2(acc[t8][2] + bv.x, acc[t8][3] + bv.y);
            *(float2*)(Cout + (size_t)row1 * DIMN + n) = o;
        }
    }
}

// ---------------- launch ----------------
extern "C" void kernel_launch(void* const* d_in, const int* in_sizes, int n_in,
                              void* d_out, int out_size) {
    const float* xu  = (const float*)d_in[0];
    const float* xi  = (const float*)d_in[1];
    const float* xt  = (const float*)d_in[2];
    const int*   eb  = (const int*)d_in[3];
    const int*   er  = (const int*)d_in[4];
    const int*   et  = (const int*)d_in[5];
    const float* WlB = (const float*)d_in[6];
    const float* WrB = (const float*)d_in[7];
    const float* bB  = (const float*)d_in[8];
    const float* WlR = (const float*)d_in[9];
    const float* WrR = (const float*)d_in[10];
    const float* bR  = (const float*)d_in[11];
    const float* WlT = (const float*)d_in[12];
    const float* WrT = (const float*)d_in[13];
    const float* bT  = (const float*)d_in[14];

    int NU = in_sizes[0] / DIMN;
    int NI = in_sizes[1] / DIMN;
    int EB = in_sizes[3] / 2;
    int ER = in_sizes[4] / 2;
    int ET = in_sizes[5] / 2;

    float* out_user = (float*)d_out;
    float* out_item = (float*)d_out + (size_t)NU * DIMN;

    int Etot = EB + ER + ET;

    // CSR build
    k_zero_cnt<<<(3 * (NU_MAX + 1) + 255) / 256, 256>>>();
    k_hist3<<<(Etot + 255) / 256, 256>>>(eb + EB, er + ER, et + ET, EB, ER, ET);
    k_scan<<<3, 1024>>>(NI, NU, NI);
    k_fill3<<<(Etot + 255) / 256, 256>>>(eb, er, et, EB, ER, ET);

    // mean aggregation
    int totalNodes = NI + NU + NI;
    k_agg3<<<(totalNodes * 32 + 255) / 256, 256>>>(xu, xi, xt, NU, NI);

    // weight prep (split/transpose + combined biases)
    k_prepW<<<(5 * 16384 + 255) / 256, 256>>>(WlR, WrR, WlB, WlT, WrB, WrT, bR, bB, bT);

    // tensor-core GEMM (mma.sync), both outputs in one launch
    const int SMEM_BYTES = 4 * 128 * TSTRIDE * 2;   // 73728
    cudaFuncSetAttribute(k_gemm_mma, cudaFuncAttributeMaxDynamicSharedMemorySize, SMEM_BYTES);
    int blocksU = (NU + 127) / 128;
    int blocksI = (NI + 127) / 128;
    k_gemm_mma<<<blocksU + blocksI, 256, SMEM_BYTES>>>(xu, xi, out_user, out_item,
                                                       NU, NI, blocksU);
}

// round 5
// speedup vs baseline: 1.6835x; 1.2823x over previous
#include <cuda_runtime.h>
#include <cuda_bf16.h>
#include <cstddef>
#include <cstdint>

#define NU_MAX 100000
#define NI_MAX 100000
#define E_MAX  1000000
#define DIMN   128

// ---------------- scratch (static __device__, no allocation) ----------------
__device__ int   g_cnt[3][NU_MAX + 1];
__device__ int   g_off[3][NU_MAX + 1];
__device__ int   g_cur[3][NU_MAX];
__device__ int   g_adj[3][E_MAX];
__device__ float g_meanB[(size_t)NI_MAX * DIMN];
__device__ float g_meanR[(size_t)NU_MAX * DIMN];
__device__ float g_meanT[(size_t)NI_MAX * DIMN];

// split + transposed weights: [panel][half hi/lo][n*128+k] bf16
__device__ __align__(16) __nv_bfloat16 g_Wsp[5][2][DIMN * DIMN];
__device__ __align__(16) float g_biasU[DIMN];
__device__ __align__(16) float g_biasI[DIMN];

// ---------------- init: zero counters + weight prep (merged) ----------------
__global__ void k_init(const float* __restrict__ WlR, const float* __restrict__ WrR,
                       const float* __restrict__ WlB, const float* __restrict__ WlT,
                       const float* __restrict__ WrB, const float* __restrict__ WrT,
                       const float* __restrict__ bR, const float* __restrict__ bB,
                       const float* __restrict__ bT) {
    int i = blockIdx.x * blockDim.x + threadIdx.x;
    const int total = 3 * (NU_MAX + 1);
    if (i < total) ((int*)g_cnt)[i] = 0;
    if (i < 5 * 16384) {
        int panel = i >> 14;
        int e = i & 16383;
        int k = e >> 7;
        int n = e & 127;
        float v;
        switch (panel) {
            case 0:  v = WlR[k * 128 + n]; break;
            case 1:  v = WrR[k * 128 + n]; break;
            case 2:  v = 0.5f * WlB[k * 128 + n]; break;
            case 3:  v = 0.5f * WlT[k * 128 + n]; break;
            default: v = 0.5f * (WrB[k * 128 + n] + WrT[k * 128 + n]);
        }
        __nv_bfloat16 h = __float2bfloat16_rn(v);
        __nv_bfloat16 l = __float2bfloat16_rn(v - __bfloat162float(h));
        g_Wsp[panel][0][n * 128 + k] = h;
        g_Wsp[panel][1][n * 128 + k] = l;
    }
    if (i < DIMN) {
        g_biasU[i] = bR[i];
        g_biasI[i] = 0.5f * (bB[i] + bT[i]);
    }
}

// ---------------- CSR build ----------------
__global__ void k_hist3(const int* __restrict__ db, const int* __restrict__ dr,
                        const int* __restrict__ dt, int EB, int ER, int ET) {
    int t = blockIdx.x * blockDim.x + threadIdx.x;
    #pragma unroll
    for (int j = 0; j < 2; j++) {
        int e = t * 2 + j;
        if (e < EB) atomicAdd(&g_cnt[0][db[e]], 1);
        else if (e < EB + ER) atomicAdd(&g_cnt[1][dr[e - EB]], 1);
        else if (e < EB + ER + ET) atomicAdd(&g_cnt[2][dt[e - EB - ER]], 1);
    }
}

// warp-shuffle based exclusive scan; 3 blocks (one per relation), 1024 threads
__global__ void k_scan(int n0, int n1, int n2) {
    int rel = blockIdx.x;
    int n = (rel == 0) ? n0 : (rel == 1) ? n1 : n2;
    int lane = threadIdx.x & 31, wid = threadIdx.x >> 5;
    __shared__ int wsum[32];
    __shared__ int carry;
    if (threadIdx.x == 0) carry = 0;
    __syncthreads();
    for (int base = 0; base < n; base += 1024) {
        int i = base + threadIdx.x;
        int v = (i < n) ? g_cnt[rel][i] : 0;
        // inclusive warp scan
        int s = v;
        #pragma unroll
        for (int d = 1; d < 32; d <<= 1) {
            int t = __shfl_up_sync(0xFFFFFFFFu, s, d);
            if (lane >= d) s += t;
        }
        if (lane == 31) wsum[wid] = s;
        __syncthreads();
        if (wid == 0) {
            int w = wsum[lane];
            #pragma unroll
            for (int d = 1; d < 32; d <<= 1) {
                int t = __shfl_up_sync(0xFFFFFFFFu, w, d);
                if (lane >= d) w += t;
            }
            wsum[lane] = w;
        }
        __syncthreads();
        int woff = (wid > 0) ? wsum[wid - 1] : 0;
        int c = carry;
        int excl = c + woff + s - v;
        if (i < n) { g_off[rel][i] = excl; g_cur[rel][i] = excl; }
        int tot = wsum[31];
        __syncthreads();
        if (threadIdx.x == 0) carry = c + tot;
        __syncthreads();
    }
    if (threadIdx.x == 0) g_off[rel][n] = carry;
}

__global__ void k_fill3(const int* __restrict__ eb, const int* __restrict__ er,
                        const int* __restrict__ et, int EB, int ER, int ET) {
    int t = blockIdx.x * blockDim.x + threadIdx.x;
    #pragma unroll
    for (int j = 0; j < 2; j++) {
        int e = t * 2 + j;
        int rel, idx;
        const int* ei;
        int E;
        if (e < EB) { rel = 0; idx = e; ei = eb; E = EB; }
        else if (e < EB + ER) { rel = 1; idx = e - EB; ei = er; E = ER; }
        else if (e < EB + ER + ET) { rel = 2; idx = e - EB - ER; ei = et; E = ET; }
        else continue;
        int d = ei[E + idx];
        int s = ei[idx];
        int p = atomicAdd(&g_cur[rel][d], 1);
        g_adj[rel][p] = s;
    }
}

// ---------------- mean aggregation: one warp per dst node, unroll-4 ----------------
__global__ void k_agg3(const float* __restrict__ xu, const float* __restrict__ xi,
                       const float* __restrict__ xt, int NU, int NI) {
    int w = (blockIdx.x * blockDim.x + threadIdx.x) >> 5;
    int lane = threadIdx.x & 31;
    int rel, node;
    const float* xs;
    float* mean;
    if (w < NI) { rel = 0; node = w; xs = xu; mean = g_meanB; }
    else if (w < NI + NU) { rel = 1; node = w - NI; xs = xi; mean = g_meanR; }
    else if (w < NI + NU + NI) { rel = 2; node = w - NI - NU; xs = xt; mean = g_meanT; }
    else return;

    const int* __restrict__ adj = g_adj[rel];
    int s0 = g_off[rel][node], s1 = g_off[rel][node + 1];
    float4 a0 = make_float4(0.f, 0.f, 0.f, 0.f);
    float4 a1 = make_float4(0.f, 0.f, 0.f, 0.f);
    float4 a2 = make_float4(0.f, 0.f, 0.f, 0.f);
    float4 a3 = make_float4(0.f, 0.f, 0.f, 0.f);
    int e = s0;
    for (; e + 3 < s1; e += 4) {
        int i0 = __ldg(&adj[e]);
        int i1 = __ldg(&adj[e + 1]);
        int i2 = __ldg(&adj[e + 2]);
        int i3 = __ldg(&adj[e + 3]);
        float4 v0 = *(const float4*)(xs + (size_t)i0 * DIMN + lane * 4);
        float4 v1 = *(const float4*)(xs + (size_t)i1 * DIMN + lane * 4);
        float4 v2 = *(const float4*)(xs + (size_t)i2 * DIMN + lane * 4);
        float4 v3 = *(const float4*)(xs + (size_t)i3 * DIMN + lane * 4);
        a0.x += v0.x; a0.y += v0.y; a0.z += v0.z; a0.w += v0.w;
        a1.x += v1.x; a1.y += v1.y; a1.z += v1.z; a1.w += v1.w;
        a2.x += v2.x; a2.y += v2.y; a2.z += v2.z; a2.w += v2.w;
        a3.x += v3.x; a3.y += v3.y; a3.z += v3.z; a3.w += v3.w;
    }
    for (; e < s1; e++) {
        int i0 = __ldg(&adj[e]);
        float4 v0 = *(const float4*)(xs + (size_t)i0 * DIMN + lane * 4);
        a0.x += v0.x; a0.y += v0.y; a0.z += v0.z; a0.w += v0.w;
    }
    a0.x += a1.x + a2.x + a3.x;
    a0.y += a1.y + a2.y + a3.y;
    a0.z += a1.z + a2.z + a3.z;
    a0.w += a1.w + a2.w + a3.w;
    int deg = s1 - s0;
    float inv = 1.0f / (float)(deg > 0 ? deg : 1);
    a0.x *= inv; a0.y *= inv; a0.z *= inv; a0.w *= inv;
    *(float4*)(mean + (size_t)node * DIMN + lane * 4) = a0;
}

// ---------------- mma.sync helpers ----------------
__device__ __forceinline__ uint32_t smem_u32(const void* p) {
    uint32_t a;
    asm("{ .reg .u64 t; cvta.to.shared.u64 t, %1; cvt.u32.u64 %0, t; }"
        : "=r"(a) : "l"(p));
    return a;
}
__device__ __forceinline__ void ldsm4(uint32_t* r, uint32_t addr) {
    asm volatile("ldmatrix.sync.aligned.m8n8.x4.shared.b16 {%0,%1,%2,%3}, [%4];"
                 : "=r"(r[0]), "=r"(r[1]), "=r"(r[2]), "=r"(r[3]) : "r"(addr));
}
__device__ __forceinline__ void mma16816(float* d, const uint32_t* a,
                                         uint32_t b0, uint32_t b1) {
    asm volatile(
        "mma.sync.aligned.m16n8k16.row.col.f32.bf16.bf16.f32 "
        "{%0,%1,%2,%3}, {%4,%5,%6,%7}, {%8,%9}, {%0,%1,%2,%3};"
        : "+f"(d[0]), "+f"(d[1]), "+f"(d[2]), "+f"(d[3])
        : "r"(a[0]), "r"(a[1]), "r"(a[2]), "r"(a[3]), "r"(b0), "r"(b1));
}
__device__ __forceinline__ void cpa16(uint32_t dst, const void* src) {
    asm volatile("cp.async.ca.shared.global [%0], [%1], 16;"
                 :: "r"(dst), "l"(src) : "memory");
}
#define CPA_COMMIT() asm volatile("cp.async.commit_group;" ::: "memory")
#define CPA_WAIT0()  asm volatile("cp.async.wait_group 0;" ::: "memory")

// ---------------- tensor-core GEMM (mma.sync bf16 3-product split) ----------------
#define TSTRIDE 72   // elements; 144 bytes

__global__ void __launch_bounds__(256, 2)
k_gemm_mma(const float* __restrict__ xu, const float* __restrict__ xi,
           float* __restrict__ out_user, float* __restrict__ out_item,
           int NU, int NI, int blocksU)
{
    extern __shared__ __nv_bfloat16 smem[];
    __nv_bfloat16* Ah = smem;
    __nv_bfloat16* Al = Ah + 128 * TSTRIDE;
    __nv_bfloat16* Wh = Al + 128 * TSTRIDE;
    __nv_bfloat16* Wl = Wh + 128 * TSTRIDE;
    const uint32_t sAh = smem_u32(Ah);
    const uint32_t sAl = smem_u32(Al);
    const uint32_t sWh = smem_u32(Wh);
    const uint32_t sWl = smem_u32(Wl);

    int tid = threadIdx.x, w = tid >> 5, lane = tid & 31;
    bool isU = (int)blockIdx.x < blocksU;
    int bidl = isU ? blockIdx.x : (blockIdx.x - blocksU);
    int m0 = bidl * 128;
    int M  = isU ? NU : NI;
    int np = isU ? 2 : 3;
    const float* Ap[3];
    int wp[3];
    if (isU) { Ap[0] = g_meanR; Ap[1] = xu; Ap[2] = xu; wp[0] = 0; wp[1] = 1; wp[2] = 1; }
    else     { Ap[0] = g_meanB; Ap[1] = g_meanT; Ap[2] = xi; wp[0] = 2; wp[1] = 3; wp[2] = 4; }
    float* Cout = isU ? out_user : out_item;
    const float* bias = isU ? g_biasU : g_biasI;

    float acc[16][4];
    #pragma unroll
    for (int i = 0; i < 16; i++)
        #pragma unroll
        for (int j = 0; j < 4; j++) acc[i][j] = 0.f;

    int a_row = lane & 15;
    int a_kh  = (lane >> 4) << 3;
    int b_n   = (lane & 7) + ((lane >> 4) << 3);
    int b_kh  = ((lane >> 3) & 1) << 3;

    // W cp.async destination for this thread (covers 128n x 64k per chunk)
    // q = tid + it*256 -> n = q>>3, j = q&7 (16B units of 8 bf16)
    for (int p = 0; p < np; p++) {
        const float* A = Ap[p];
        const __nv_bfloat16* WHsrc = g_Wsp[wp[p]][0];
        const __nv_bfloat16* WLsrc = g_Wsp[wp[p]][1];
        for (int c = 0; c < 2; c++) {
            __syncthreads();   // protect previous iteration's smem reads
            // ---- W chunk via cp.async (overlaps with A convert below)
            #pragma unroll
            for (int it = 0; it < 4; it++) {
                int q = tid + it * 256;
                int n = q >> 3;
                int j = q & 7;
                cpa16(sWh + (n * TSTRIDE + j * 8) * 2, WHsrc + n * 128 + c * 64 + j * 8);
                cpa16(sWl + (n * TSTRIDE + j * 8) * 2, WLsrc + n * 128 + c * 64 + j * 8);
            }
            CPA_COMMIT();
            // ---- load & split A chunk [128 m x 64 k]
            #pragma unroll
            for (int it = 0; it < 8; it++) {
                int q = tid + it * 256;
                int row = q >> 4;
                int k4  = (q & 15) << 2;
                int grow = m0 + row;
                float4 v = make_float4(0.f, 0.f, 0.f, 0.f);
                if (grow < M) v = *(const float4*)(A + (size_t)grow * DIMN + c * 64 + k4);
                __nv_bfloat16 h0 = __float2bfloat16_rn(v.x);
                __nv_bfloat16 h1 = __float2bfloat16_rn(v.y);
                __nv_bfloat16 h2 = __float2bfloat16_rn(v.z);
                __nv_bfloat16 h3 = __float2bfloat16_rn(v.w);
                ushort4 uh = make_ushort4(__bfloat16_as_ushort(h0), __bfloat16_as_ushort(h1),
                                          __bfloat16_as_ushort(h2), __bfloat16_as_ushort(h3));
                __nv_bfloat16 l0 = __float2bfloat16_rn(v.x - __bfloat162float(h0));
                __nv_bfloat16 l1 = __float2bfloat16_rn(v.y - __bfloat162float(h1));
                __nv_bfloat16 l2 = __float2bfloat16_rn(v.z - __bfloat162float(h2));
                __nv_bfloat16 l3 = __float2bfloat16_rn(v.w - __bfloat162float(h3));
                ushort4 ul = make_ushort4(__bfloat16_as_ushort(l0), __bfloat16_as_ushort(l1),
                                          __bfloat16_as_ushort(l2), __bfloat16_as_ushort(l3));
                *(ushort4*)(Ah + row * TSTRIDE + k4) = uh;
                *(ushort4*)(Al + row * TSTRIDE + k4) = ul;
            }
            CPA_WAIT0();
            __syncthreads();
            // ---- compute: warp w owns rows [w*16, w*16+16)
            #pragma unroll
            for (int ks = 0; ks < 4; ks++) {
                uint32_t aH[4], aL[4];
                uint32_t aoff = (w * 16 + a_row) * (TSTRIDE * 2) + (ks * 16 + a_kh) * 2;
                ldsm4(aH, sAh + aoff);
                ldsm4(aL, sAl + aoff);
                #pragma unroll
                for (int nt = 0; nt < 8; nt++) {
                    uint32_t bH[4], bL[4];
                    uint32_t boff = (nt * 16 + b_n) * (TSTRIDE * 2) + (ks * 16 + b_kh) * 2;
                    ldsm4(bH, sWh + boff);
                    ldsm4(bL, sWl + boff);
                    mma16816(acc[nt * 2],     aH, bH[0], bH[1]);
                    mma16816(acc[nt * 2 + 1], aH, bH[2], bH[3]);
                    mma16816(acc[nt * 2],     aH, bL[0], bL[1]);
                    mma16816(acc[nt * 2 + 1], aH, bL[2], bL[3]);
                    mma16816(acc[nt * 2],     aL, bH[0], bH[1]);
                    mma16816(acc[nt * 2 + 1], aL, bH[2], bH[3]);
                }
            }
        }
    }

    // ---- epilogue
    int row0 = m0 + w * 16 + (lane >> 2);
    int row1 = row0 + 8;
    int ncol = (lane & 3) * 2;
    #pragma unroll
    for (int t8 = 0; t8 < 16; t8++) {
        int n = t8 * 8 + ncol;
        float2 bv = *(const float2*)(bias + n);
        if (row0 < M) {
            float2 o = make_float2(acc[t8][0] + bv.x, acc[t8][1] + bv.y);
            *(float2*)(Cout + (size_t)row0 * DIMN + n) = o;
        }
        if (row1 < M) {
            float2 o = make_float2(acc[t8][2] + bv.x, acc[t8][3] + bv.y);
            *(float2*)(Cout + (size_t)row1 * DIMN + n) = o;
        }
    }
}

// ---------------- launch ----------------
extern "C" void kernel_launch(void* const* d_in, const int* in_sizes, int n_in,
                              void* d_out, int out_size) {
    const float* xu  = (const float*)d_in[0];
    const float* xi  = (const float*)d_in[1];
    const float* xt  = (const float*)d_in[2];
    const int*   eb  = (const int*)d_in[3];
    const int*   er  = (const int*)d_in[4];
    const int*   et  = (const int*)d_in[5];
    const float* WlB = (const float*)d_in[6];
    const float* WrB = (const float*)d_in[7];
    const float* bB  = (const float*)d_in[8];
    const float* WlR = (const float*)d_in[9];
    const float* WrR = (const float*)d_in[10];
    const float* bR  = (const float*)d_in[11];
    const float* WlT = (const float*)d_in[12];
    const float* WrT = (const float*)d_in[13];
    const float* bT  = (const float*)d_in[14];

    int NU = in_sizes[0] / DIMN;
    int NI = in_sizes[1] / DIMN;
    int EB = in_sizes[3] / 2;
    int ER = in_sizes[4] / 2;
    int ET = in_sizes[5] / 2;

    float* out_user = (float*)d_out;
    float* out_item = (float*)d_out + (size_t)NU * DIMN;

    int Etot = EB + ER + ET;

    // init (zero counters + weight prep)
    k_init<<<(3 * (NU_MAX + 1) + 255) / 256, 256>>>(WlR, WrR, WlB, WlT, WrB, WrT,
                                                    bR, bB, bT);
    // CSR build
    k_hist3<<<(Etot / 2 + 256) / 256, 256>>>(eb + EB, er + ER, et + ET, EB, ER, ET);
    k_scan<<<3, 1024>>>(NI, NU, NI);
    k_fill3<<<(Etot / 2 + 256) / 256, 256>>>(eb, er, et, EB, ER, ET);

    // mean aggregation
    int totalNodes = NI + NU + NI;
    k_agg3<<<(totalNodes * 32 + 255) / 256, 256>>>(xu, xi, xt, NU, NI);

    // tensor-core GEMM (mma.sync), both outputs in one launch
    const int SMEM_BYTES = 4 * 128 * TSTRIDE * 2;   // 73728
    cudaFuncSetAttribute(k_gemm_mma, cudaFuncAttributeMaxDynamicSharedMemorySize, SMEM_BYTES);
    int blocksU = (NU + 127) / 128;
    int blocksI = (NI + 127) / 128;
    k_gemm_mma<<<blocksU + blocksI, 256, SMEM_BYTES>>>(xu, xi, out_user, out_item,
                                                       NU, NI, blocksU);
}